// round 1
// baseline (speedup 1.0000x reference)
#include <cuda_runtime.h>

#define B_   256
#define TIN  49
#define TOUT 25
#define NB   24
#define H    128
#define G5   640   // 5*H
// out row stride for batch dim in [B, TOUT, NB, H]
#define OSTRIDE (TOUT*NB*H)

// ---------------- scratch (static device globals; no allocations) ----------------
__device__ float g_row_h0[NB*B_*H];          // [NB][B][H] mean_t hidden
__device__ float g_row_h1[NB*B_*H];          // [NB][B][H] mean_t (global ++ hidden)
__device__ float g_row_c [NB*B_*H];          // [NB][B][H] mean_t cell
__device__ float g_col_h [B_*H];             // [B][H] mean_{t,j} hidden
__device__ float g_col_c [B_*H];             // [B][H] mean_{t,j} cell
__device__ float g_xu0  [TOUT*NB*B_*G5];     // p @ U[0] + b[0]   (~393 MB)
__device__ float g_h0   [TOUT*NB*B_*H];      // rec-0 h grid
__device__ float g_c0   [TOUT*NB*B_*H];      // rec-0 c grid
__device__ float g_z    [24*B_*G5];          // per-step z scratch (24 cell slots)

typedef unsigned long long u64;

__device__ __forceinline__ u64 pack2(float x, float y){
    u64 r; asm("mov.b64 %0, {%1,%2};" : "=l"(r) : "f"(x), "f"(y)); return r;
}
__device__ __forceinline__ void unpack2(u64 v, float& x, float& y){
    asm("mov.b64 {%0,%1}, %2;" : "=f"(x), "=f"(y) : "l"(v));
}
__device__ __forceinline__ u64 ffma2(u64 a, u64 b, u64 c){
    u64 d; asm("fma.rn.f32x2 %0, %1, %2, %3;" : "=l"(d) : "l"(a), "l"(b), "l"(c)); return d;
}

// ---------------- phase 0: boundary reductions ----------------
__global__ void rows_kernel(const float* __restrict__ hid,
                            const float* __restrict__ cel,
                            const float* __restrict__ gts)
{
    int gid = blockIdx.x*256 + threadIdx.x;        // over NB*B*H
    int j = gid / (B_*H);
    int rem = gid - j*(B_*H);
    int b = rem >> 7, h = rem & 127;
    const float* ph = hid + (b*TIN*NB + j)*H + h;
    const float* pc = cel + (b*TIN*NB + j)*H + h;
    float sh = 0.f, sc = 0.f;
    for (int t = 0; t < TIN; ++t) { sh += ph[t*NB*H]; sc += pc[t*NB*H]; }
    int o = (j*B_ + b)*H + h;
    g_row_h0[o] = sh * (1.0f/TIN);
    g_row_h1[o] = (gts[(b*NB + j)*H + h] + sh) * (1.0f/(TIN+1));
    g_row_c [o] = sc * (1.0f/TIN);
}

__global__ void cols_kernel()
{
    int gid = blockIdx.x*256 + threadIdx.x;        // over B*H
    float sh = 0.f, sc = 0.f;
#pragma unroll
    for (int j = 0; j < NB; ++j) {
        sh += g_row_h0[j*B_*H + gid];
        sc += g_row_c [j*B_*H + gid];
    }
    g_col_h[gid] = sh * (1.0f/NB);
    g_col_c[gid] = sc * (1.0f/NB);
}

// ---------------- fp32 GEMM core (FFMA2), 128x128 tile, BK=16, 256 thr ----------------
struct Src { const float* A; int lda; const float* W; };

__device__ __forceinline__ void gemm_tile(const Src* src, int ns, float* Cbase,
                                          const float* bias)
{
    __shared__ float sA[16][128];
    __shared__ float sB[16][128];

    const int tid = threadIdx.x;
    const int m0 = (blockIdx.x & 1) * 128;
    const int n0 = (blockIdx.x >> 1) * 128;

    const int a_m = tid >> 1;            // 0..127
    const int a_k = (tid & 1) * 8;       // 0 / 8
    const int b_k = tid >> 4;            // 0..15
    const int b_n = (tid & 15) * 8;      // 0..120

    const int mreg = (tid >> 4) * 8;
    const int nreg = (tid & 15) * 8;

    u64 acc[8][4];
#pragma unroll
    for (int i = 0; i < 8; ++i)
#pragma unroll
        for (int jj = 0; jj < 4; ++jj) acc[i][jj] = 0ull;

    const int total = ns * 8;            // 8 chunks of 16 per 128-K source
    float4 pa0, pa1, pb0, pb1;
    {
        const float* Ag = src[0].A + (m0 + a_m)*src[0].lda + a_k;
        pa0 = *(const float4*)Ag;  pa1 = *(const float4*)(Ag + 4);
        const float* Bg = src[0].W + b_k*G5 + n0 + b_n;
        pb0 = *(const float4*)Bg;  pb1 = *(const float4*)(Bg + 4);
    }
    for (int c = 0; c < total; ++c) {
#pragma unroll
        for (int i = 0; i < 4; ++i) {
            sA[a_k + i    ][a_m] = ((float*)&pa0)[i];
            sA[a_k + 4 + i][a_m] = ((float*)&pa1)[i];
        }
        *(float4*)&sB[b_k][b_n]     = pb0;
        *(float4*)&sB[b_k][b_n + 4] = pb1;
        __syncthreads();
        if (c + 1 < total) {                       // prefetch next chunk
            const int cn = c + 1;
            const Src s = src[cn >> 3];
            const int kk = (cn & 7) * 16;
            const float* Ag = s.A + (m0 + a_m)*s.lda + kk + a_k;
            pa0 = *(const float4*)Ag;  pa1 = *(const float4*)(Ag + 4);
            const float* Bg = s.W + (kk + b_k)*G5 + n0 + b_n;
            pb0 = *(const float4*)Bg;  pb1 = *(const float4*)(Bg + 4);
        }
#pragma unroll
        for (int k = 0; k < 16; ++k) {
            float4 a0 = *(const float4*)&sA[k][mreg];
            float4 a1 = *(const float4*)&sA[k][mreg + 4];
            ulonglong2 bb0 = *(const ulonglong2*)&sB[k][nreg];
            ulonglong2 bb1 = *(const ulonglong2*)&sB[k][nreg + 4];
            u64 bv0 = bb0.x, bv1 = bb0.y, bv2 = bb1.x, bv3 = bb1.y;
            float av[8] = {a0.x,a0.y,a0.z,a0.w,a1.x,a1.y,a1.z,a1.w};
#pragma unroll
            for (int i = 0; i < 8; ++i) {
                u64 ad = pack2(av[i], av[i]);
                acc[i][0] = ffma2(ad, bv0, acc[i][0]);
                acc[i][1] = ffma2(ad, bv1, acc[i][1]);
                acc[i][2] = ffma2(ad, bv2, acc[i][2]);
                acc[i][3] = ffma2(ad, bv3, acc[i][3]);
            }
        }
        __syncthreads();
    }
#pragma unroll
    for (int i = 0; i < 8; ++i) {
        float* Crow = Cbase + (m0 + mreg + i)*G5 + n0 + nreg;
#pragma unroll
        for (int jj = 0; jj < 4; ++jj) {
            float x, y; unpack2(acc[i][jj], x, y);
            if (bias) { x += bias[n0 + nreg + 2*jj]; y += bias[n0 + nreg + 2*jj + 1]; }
            float2 v; v.x = x; v.y = y;
            *(float2*)(Crow + 2*jj) = v;
        }
    }
}

// ---------------- phase 1: xU0 = p @ U[0] + b[0] ----------------
__global__ __launch_bounds__(256) void gemm_xu0_kernel(const float* __restrict__ p,
                                                       const float* __restrict__ U,
                                                       const float* __restrict__ bvec)
{
    int cell = blockIdx.y;
    int t = cell / NB, j = cell - t*NB;
    Src s[1];
    s[0].A = p + (t*NB + j)*H;  s[0].lda = OSTRIDE;  s[0].W = U + j*H*G5;
    gemm_tile(s, 1, g_xu0 + (long)cell*B_*G5, bvec + j*G5);
}

// ---------------- phase 2: wavefront steps ----------------
struct StepList { int n; int cells[24]; };

__global__ __launch_bounds__(256) void gemm_step_kernel(StepList sl,
                                                        const float* __restrict__ U,
                                                        const float* __restrict__ Wt,
                                                        const float* __restrict__ Ws,
                                                        const float* __restrict__ outH)
{
    int code = sl.cells[blockIdx.y];
    int r = code >> 16, t = (code >> 8) & 255, j = code & 255;
    Src s[3]; int ns;
    if (r == 0) {
        ns = 2;
        s[0].A = (t == 0) ? g_row_h0 + j*B_*H : g_h0 + ((t-1)*NB + j)*B_*H;
        s[0].lda = H;  s[0].W = Wt + j*H*G5;
        s[1].A = (j == 0) ? g_col_h : g_h0 + (t*NB + (j-1))*B_*H;
        s[1].lda = H;  s[1].W = Ws + j*H*G5;
    } else {
        ns = 3;
        s[0].A = g_h0 + (t*NB + j)*B_*H;  s[0].lda = H;  s[0].W = U + (NB + j)*H*G5;
        if (t == 0) { s[1].A = g_row_h1 + j*B_*H;          s[1].lda = H; }
        else        { s[1].A = outH + ((t-1)*NB + j)*H;    s[1].lda = OSTRIDE; }
        s[1].W = Wt + (NB + j)*H*G5;
        if (j == 0) { s[2].A = g_col_h;                    s[2].lda = H; }
        else        { s[2].A = outH + (t*NB + (j-1))*H;    s[2].lda = OSTRIDE; }
        s[2].W = Ws + (NB + j)*H*G5;
    }
    gemm_tile(s, ns, g_z + blockIdx.y*B_*G5, nullptr);
}

__device__ __forceinline__ float sigf(float x){ return 1.0f/(1.0f + __expf(-x)); }
__device__ __forceinline__ float tanhfast(float x){ return 2.0f*sigf(2.0f*x) - 1.0f; }

__global__ __launch_bounds__(256) void ew_step_kernel(StepList sl,
                                                      const float* __restrict__ bvec,
                                                      float* __restrict__ outH)
{
    int code = sl.cells[blockIdx.y];
    int r = code >> 16, t = (code >> 8) & 255, j = code & 255;
    int e = blockIdx.x*256 + threadIdx.x;      // 0..B*H-1
    int m = e >> 7, h = e & 127;
    const float* zb = g_z + blockIdx.y*B_*G5 + m*G5 + h;
    float z0 = zb[0], z1 = zb[128], z2 = zb[256], z3 = zb[384], z4 = zb[512];
    float ct, cs;
    float* outC = outH + (long)B_*TOUT*NB*H;
    if (r == 0) {
        const float* xb = g_xu0 + ((long)(t*NB + j)*B_ + m)*G5 + h;
        z0 += xb[0]; z1 += xb[128]; z2 += xb[256]; z3 += xb[384]; z4 += xb[512];
        ct = (t == 0) ? g_row_c[(j*B_ + m)*H + h]
                      : g_c0[(((t-1)*NB + j)*B_ + m)*H + h];
        cs = (j == 0) ? g_col_c[m*H + h]
                      : g_c0[((t*NB + (j-1))*B_ + m)*H + h];
    } else {
        const float* bb = bvec + (NB + j)*G5 + h;
        z0 += bb[0]; z1 += bb[128]; z2 += bb[256]; z3 += bb[384]; z4 += bb[512];
        ct = (t == 0) ? g_row_c[(j*B_ + m)*H + h]
                      : outC[((m*TOUT + (t-1))*NB + j)*H + h];
        cs = (j == 0) ? g_col_c[m*H + h]
                      : outC[((m*TOUT + t)*NB + (j-1))*H + h];
    }
    // gate order: i, f_s, f_t, o, g
    float in_ = sigf(z0), fs = sigf(z1), ft = sigf(z2), o = sigf(z3), g = tanhfast(z4);
    float c  = in_*g + ft*ct + fs*cs;
    float hv = o * tanhfast(c);
    if (r == 0) {
        int idx = ((t*NB + j)*B_ + m)*H + h;
        g_h0[idx] = hv;  g_c0[idx] = c;
    } else {
        int idx = ((m*TOUT + t)*NB + j)*H + h;
        outH[idx] = hv;  outC[idx] = c;
    }
}

// ---------------- launch ----------------
extern "C" void kernel_launch(void* const* d_in, const int* in_sizes, int n_in,
                              void* d_out, int out_size)
{
    const float* hid = (const float*)d_in[0];
    const float* cel = (const float*)d_in[1];
    const float* gts = (const float*)d_in[2];
    const float* p   = (const float*)d_in[3];
    const float* U   = (const float*)d_in[4];
    const float* Wt  = (const float*)d_in[5];
    const float* Ws  = (const float*)d_in[6];
    const float* bv  = (const float*)d_in[7];
    float* outH = (float*)d_out;

    rows_kernel<<<NB*B_*H/256, 256>>>(hid, cel, gts);
    cols_kernel<<<B_*H/256, 256>>>();
    gemm_xu0_kernel<<<dim3(10, TOUT*NB), 256>>>(p, U, bv);

    // wavefront: d = 2t + j + r, d in [0, 72]
    for (int d = 0; d <= 2*(TOUT-1) + (NB-1) + 1; ++d) {
        StepList sl; sl.n = 0;
        for (int t = 0; t < TOUT; ++t) {               // rec 0: 2t + j = d
            int j = d - 2*t;
            if (j >= 0 && j < NB) sl.cells[sl.n++] = (0 << 16) | (t << 8) | j;
        }
        for (int t = 0; t < TOUT; ++t) {               // rec 1: 2t + j = d - 1
            int j = d - 1 - 2*t;
            if (j >= 0 && j < NB) sl.cells[sl.n++] = (1 << 16) | (t << 8) | j;
        }
        if (!sl.n) continue;
        gemm_step_kernel<<<dim3(10, sl.n), 256>>>(sl, U, Wt, Ws, outH);
        ew_step_kernel<<<dim3(B_*H/256, sl.n), 256>>>(sl, bv, outH);
    }
}